// round 6
// baseline (speedup 1.0000x reference)
#include <cuda_runtime.h>
#include <cuda_bf16.h>
#include <math.h>

// AdaptiveGraphGenerator: dim=128, B=1, N=1024.
// edge predictor is dead code (edge_probs = ones). adj = (1.0 > threshold).
// Real work: node encoder LN(x@W1+b1) -> GELU -> @W2+b2.
//
// R6: packed f32x2 FFMA2 GEMM loops.
//  - weights loaded as ulonglong2 (LDG.128 -> two packed (w_j,w_j+1) pairs, 0 packs)
//  - x / gelu(h) stored PRE-SPLATTED as float2(v,v) in shared -> LDS.64 broadcast
//  - inner iter: 1 LDG.128 + 2 LDS.64 + 4 FFMA2 = 7 instr / 16 MACs (was 11)
//  - scratch combine / LN identical to R5 (accumulator bit-layout unchanged)
// 512 blocks x 256 threads, 2 rows/block, weights read once per block.

#define DIM 128
#define HID 256
#define NROWS 1024
#define ROWS 2
#define THREADS 256
#define NBLOCKS (NROWS / ROWS)   // 512

typedef unsigned long long u64t;

__device__ __forceinline__ float gelu_exact(float v) {
    return 0.5f * v * (1.0f + erff(v * 0.70710678118654752f));
}

__device__ __forceinline__ u64t ffma2(u64t a, u64t b, u64t c) {
    u64t d;
    asm("fma.rn.f32x2 %0, %1, %2, %3;" : "=l"(d) : "l"(a), "l"(b), "l"(c));
    return d;
}

__device__ __forceinline__ float2 unpack2(u64t v) {
    float2 f;
    asm("mov.b64 {%0, %1}, %2;" : "=f"(f.x), "=f"(f.y) : "l"(v));
    return f;
}

__global__ __launch_bounds__(THREADS, 4)
void fused_kernel(const float* __restrict__ x,
                  const float* __restrict__ W1,
                  const float* __restrict__ b1,
                  const float* __restrict__ ln_g,
                  const float* __restrict__ ln_b,
                  const float* __restrict__ W2,
                  const float* __restrict__ b2,
                  const float* __restrict__ thr,
                  float* __restrict__ adj_out,
                  float* __restrict__ node_out) {
    __shared__ float2 sxp[ROWS][DIM];      // 2 KB  splatted x: (v,v)
    __shared__ float2 shp[ROWS][HID];      // 4 KB  splatted gelu(h): (v,v)
    __shared__ float scratch[2048];        // 8 KB  p1[4][2][256] then p2[8][2][128]
    __shared__ float s_sum[8][ROWS];
    __shared__ float s_sq[8][ROWS];

    const int tid  = threadIdx.x;           // 0..255
    const int row0 = blockIdx.x * ROWS;

    // ---- early scalar prefetches (latency hidden under GEMM1) ----
    const float tv    = __ldg(&thr[0]);
    const float bias1 = __ldg(&b1[tid]);
    const float gg    = __ldg(&ln_g[tid]);
    const float bb    = __ldg(&ln_b[tid]);
    const float bias2 = __ldg(&b2[tid & (DIM - 1)]);

    // ---- load x tile [2,128], store splatted (thread t -> r=t>>7, c=t&127) ----
    {
        const int r = tid >> 7;
        const int c = tid & (DIM - 1);
        const float v = __ldg(&x[(size_t)(row0 + r) * DIM + c]);
        sxp[r][c] = make_float2(v, v);
    }

    // ---- adj fill: this block's 2048-float slice (512 float4) ----
    {
        const float v = (1.0f > tv) ? 1.0f : 0.0f;
        const float4 f4 = make_float4(v, v, v, v);
        float4* a4 = reinterpret_cast<float4*>(adj_out) + (size_t)blockIdx.x * 512;
        a4[tid]       = f4;
        a4[tid + 256] = f4;
    }
    __syncthreads();

    // ---- GEMM1: cg = tid&63 -> cols 4cg..4cg+3, h = tid>>6 -> k in [32h,32h+32)
    //      W1 read once per block via LDG.128 (as 2 packed col-pairs). ----
    {
        const int cg = tid & 63;
        const int h  = tid >> 6;            // 0..3
        const float* w1p = W1 + (size_t)(h * 32) * HID + 4 * cg;
        const float2* x0p = &sxp[0][h * 32];
        const float2* x1p = &sxp[1][h * 32];
        u64t r0a = 0ULL, r0b = 0ULL, r1a = 0ULL, r1b = 0ULL;
        #pragma unroll 8
        for (int kk = 0; kk < 32; kk++) {
            const ulonglong2 wp =
                *reinterpret_cast<const ulonglong2*>(w1p + (size_t)kk * HID);
            const u64t x0 = *reinterpret_cast<const u64t*>(&x0p[kk]);
            const u64t x1 = *reinterpret_cast<const u64t*>(&x1p[kk]);
            r0a = ffma2(x0, wp.x, r0a);
            r0b = ffma2(x0, wp.y, r0b);
            r1a = ffma2(x1, wp.x, r1a);
            r1b = ffma2(x1, wp.y, r1b);
        }
        const float2 f0a = unpack2(r0a), f0b = unpack2(r0b);
        const float2 f1a = unpack2(r1a), f1b = unpack2(r1b);
        *reinterpret_cast<float4*>(&scratch[(h * 2 + 0) * 256 + 4 * cg]) =
            make_float4(f0a.x, f0a.y, f0b.x, f0b.y);
        *reinterpret_cast<float4*>(&scratch[(h * 2 + 1) * 256 + 4 * cg]) =
            make_float4(f1a.x, f1a.y, f1b.x, f1b.y);
    }
    __syncthreads();

    // ---- combine k-partials + LN stats (thread t owns col c = t, both rows) ----
    float v0, v1;
    {
        const int c = tid;
        v0 = scratch[0 * 512 + c]       + scratch[1 * 512 + c]
           + scratch[2 * 512 + c]       + scratch[3 * 512 + c] + bias1;
        v1 = scratch[0 * 512 + 256 + c] + scratch[1 * 512 + 256 + c]
           + scratch[2 * 512 + 256 + c] + scratch[3 * 512 + 256 + c] + bias1;

        const int wid  = tid >> 5;
        const int lane = tid & 31;
        float s0 = v0, q0 = v0 * v0, s1 = v1, q1 = v1 * v1;
        #pragma unroll
        for (int o = 16; o > 0; o >>= 1) {
            s0 += __shfl_xor_sync(0xffffffffu, s0, o);
            q0 += __shfl_xor_sync(0xffffffffu, q0, o);
            s1 += __shfl_xor_sync(0xffffffffu, s1, o);
            q1 += __shfl_xor_sync(0xffffffffu, q1, o);
        }
        if (lane == 0) {
            s_sum[wid][0] = s0; s_sq[wid][0] = q0;
            s_sum[wid][1] = s1; s_sq[wid][1] = q1;
        }
    }
    __syncthreads();

    // ---- per-thread LN finalize + GELU -> splatted shp ----
    {
        float s0 = 0.f, q0 = 0.f, s1 = 0.f, q1 = 0.f;
        #pragma unroll
        for (int w = 0; w < 8; w++) {
            s0 += s_sum[w][0]; q0 += s_sq[w][0];
            s1 += s_sum[w][1]; q1 += s_sq[w][1];
        }
        const float m0 = s0 * (1.0f / HID);
        const float m1 = s1 * (1.0f / HID);
        const float r0 = rsqrtf(q0 * (1.0f / HID) - m0 * m0 + 1e-5f);
        const float r1 = rsqrtf(q1 * (1.0f / HID) - m1 * m1 + 1e-5f);
        const float g0 = gelu_exact((v0 - m0) * r0 * gg + bb);
        const float g1 = gelu_exact((v1 - m1) * r1 * gg + bb);
        shp[0][tid] = make_float2(g0, g0);
        shp[1][tid] = make_float2(g1, g1);
    }
    __syncthreads();

    // ---- GEMM2: cg2 = tid&31 -> cols 4cg2..+3, h2 = tid>>5 -> k in [32h2,32h2+32)
    //      W2 read once per block via LDG.128 (packed col-pairs). ----
    {
        const int cg2 = tid & 31;
        const int h2  = tid >> 5;           // 0..7
        const float* w2p = W2 + (size_t)(h2 * 32) * DIM + 4 * cg2;
        const float2* g0p = &shp[0][h2 * 32];
        const float2* g1p = &shp[1][h2 * 32];
        u64t r0a = 0ULL, r0b = 0ULL, r1a = 0ULL, r1b = 0ULL;
        #pragma unroll 8
        for (int kk = 0; kk < 32; kk++) {
            const ulonglong2 wp =
                *reinterpret_cast<const ulonglong2*>(w2p + (size_t)kk * DIM);
            const u64t g0 = *reinterpret_cast<const u64t*>(&g0p[kk]);
            const u64t g1 = *reinterpret_cast<const u64t*>(&g1p[kk]);
            r0a = ffma2(g0, wp.x, r0a);
            r0b = ffma2(g0, wp.y, r0b);
            r1a = ffma2(g1, wp.x, r1a);
            r1b = ffma2(g1, wp.y, r1b);
        }
        const float2 f0a = unpack2(r0a), f0b = unpack2(r0b);
        const float2 f1a = unpack2(r1a), f1b = unpack2(r1b);
        *reinterpret_cast<float4*>(&scratch[(h2 * 2 + 0) * 128 + 4 * cg2]) =
            make_float4(f0a.x, f0a.y, f0b.x, f0b.y);
        *reinterpret_cast<float4*>(&scratch[(h2 * 2 + 1) * 128 + 4 * cg2]) =
            make_float4(f1a.x, f1a.y, f1b.x, f1b.y);
    }
    __syncthreads();

    // ---- combine GEMM2 k-partials + store (thread t -> row tid>>7, col tid&127) ----
    {
        const int r = tid >> 7;
        const int c = tid & (DIM - 1);
        float o = bias2;
        #pragma unroll
        for (int hh = 0; hh < 8; hh++)
            o += scratch[(hh * 2 + r) * 128 + c];
        node_out[(size_t)(row0 + r) * DIM + c] = o;
    }
}

extern "C" void kernel_launch(void* const* d_in, const int* in_sizes, int n_in,
                              void* d_out, int out_size) {
    const float* x    = (const float*)d_in[0];
    const float* W1   = (const float*)d_in[1];
    const float* b1   = (const float*)d_in[2];
    const float* ln_g = (const float*)d_in[3];
    const float* ln_b = (const float*)d_in[4];
    const float* W2   = (const float*)d_in[5];
    const float* b2   = (const float*)d_in[6];
    const float* thr  = (const float*)d_in[11];

    float* out = (float*)d_out;
    float* adj_out  = out;                      // [1,1024,1024,1]
    float* node_out = out + NROWS * NROWS;      // [1,1024,128]

    fused_kernel<<<NBLOCKS, THREADS>>>(x, W1, b1, ln_g, ln_b, W2, b2, thr,
                                       adj_out, node_out);
}

// round 8
// speedup vs baseline: 1.1629x; 1.1629x over previous
#include <cuda_runtime.h>
#include <cuda_bf16.h>
#include <math.h>

// AdaptiveGraphGenerator: dim=128, B=1, N=1024.
// edge predictor is dead code (edge_probs = ones). adj = (1.0 > threshold).
// Real work: node encoder LN(x@W1+b1) -> GELU -> @W2+b2.
//
// R8 (= R7 resubmit; prior round was an infra container failure):
// scalar FFMA, ROWS=4 x 512 threads x 256 blocks. Weight matrices read once
// per block via LDG.128 and amortized over 4 rows (halves L1 weight traffic
// vs R5). k-split partials combined via 32KB shared scratch.

#define DIM 128
#define HID 256
#define NROWS 1024
#define ROWS 4
#define THREADS 512
#define NBLOCKS (NROWS / ROWS)   // 256

__device__ __forceinline__ float gelu_exact(float v) {
    return 0.5f * v * (1.0f + erff(v * 0.70710678118654752f));
}

__global__ __launch_bounds__(THREADS, 2)
void fused_kernel(const float* __restrict__ x,
                  const float* __restrict__ W1,
                  const float* __restrict__ b1,
                  const float* __restrict__ ln_g,
                  const float* __restrict__ ln_b,
                  const float* __restrict__ W2,
                  const float* __restrict__ b2,
                  const float* __restrict__ thr,
                  float* __restrict__ adj_out,
                  float* __restrict__ node_out) {
    __shared__ float sx[ROWS][DIM];        // 2 KB
    __shared__ float sh[ROWS][HID];        // 4 KB  gelu(h)
    __shared__ float scratch[8192];        // 32 KB: p1[8][4][256] then p2[16][4][128]
    __shared__ float s_sum[16][2];
    __shared__ float s_sq[16][2];

    const int tid  = threadIdx.x;           // 0..511
    const int row0 = blockIdx.x * ROWS;

    // ---- early scalar prefetches (latency hidden under GEMM1) ----
    const float tv    = __ldg(&thr[0]);
    const float bias1 = __ldg(&b1[tid & 255]);
    const float gg    = __ldg(&ln_g[tid & 255]);
    const float bb    = __ldg(&ln_b[tid & 255]);
    const float bias2 = __ldg(&b2[tid & (DIM - 1)]);

    // ---- load x tile [4,128] (thread t -> r=t>>7, c=t&127) ----
    {
        const int r = tid >> 7;
        const int c = tid & (DIM - 1);
        sx[r][c] = __ldg(&x[(size_t)(row0 + r) * DIM + c]);
    }

    // ---- adj fill: this block's 4096-float slice (1024 float4) ----
    {
        const float v = (1.0f > tv) ? 1.0f : 0.0f;
        const float4 f4 = make_float4(v, v, v, v);
        float4* a4 = reinterpret_cast<float4*>(adj_out) + (size_t)blockIdx.x * 1024;
        a4[tid]       = f4;
        a4[tid + 512] = f4;
    }
    __syncthreads();

    // ---- GEMM1: cg = tid&63 -> cols 4cg..4cg+3, h = tid>>6 (8 slices) ->
    //      k in [16h,16h+16). W1 read once per block via LDG.128. ----
    {
        const int cg = tid & 63;
        const int h  = tid >> 6;            // 0..7
        const float* w1p = W1 + (size_t)(h * 16) * HID + 4 * cg;
        float4 a0 = make_float4(0.f, 0.f, 0.f, 0.f);
        float4 a1 = a0, a2 = a0, a3 = a0;
        #pragma unroll 4
        for (int kk = 0; kk < 16; kk++) {
            const float4 w4 = *reinterpret_cast<const float4*>(w1p + (size_t)kk * HID);
            const int k = h * 16 + kk;
            const float x0 = sx[0][k];
            const float x1 = sx[1][k];
            const float x2 = sx[2][k];
            const float x3 = sx[3][k];
            a0.x = fmaf(x0, w4.x, a0.x); a0.y = fmaf(x0, w4.y, a0.y);
            a0.z = fmaf(x0, w4.z, a0.z); a0.w = fmaf(x0, w4.w, a0.w);
            a1.x = fmaf(x1, w4.x, a1.x); a1.y = fmaf(x1, w4.y, a1.y);
            a1.z = fmaf(x1, w4.z, a1.z); a1.w = fmaf(x1, w4.w, a1.w);
            a2.x = fmaf(x2, w4.x, a2.x); a2.y = fmaf(x2, w4.y, a2.y);
            a2.z = fmaf(x2, w4.z, a2.z); a2.w = fmaf(x2, w4.w, a2.w);
            a3.x = fmaf(x3, w4.x, a3.x); a3.y = fmaf(x3, w4.y, a3.y);
            a3.z = fmaf(x3, w4.z, a3.z); a3.w = fmaf(x3, w4.w, a3.w);
        }
        // p1[h][r][c] = scratch[(h*4+r)*256 + c]; STS.128 conflict-free
        float4* sc = reinterpret_cast<float4*>(scratch);
        sc[((h * 4 + 0) * 256 + 4 * cg) >> 2] = a0;
        sc[((h * 4 + 1) * 256 + 4 * cg) >> 2] = a1;
        sc[((h * 4 + 2) * 256 + 4 * cg) >> 2] = a2;
        sc[((h * 4 + 3) * 256 + 4 * cg) >> 2] = a3;
    }
    __syncthreads();

    // ---- combine k-partials + LN stats.
    //      thread t: c = t&255, rh = t>>8 -> rows {2rh, 2rh+1}.
    //      warps 0-7 -> rows 0,1; warps 8-15 -> rows 2,3. ----
    float v0, v1;
    const int rh = tid >> 8;
    {
        const int c  = tid & 255;
        const int r0 = 2 * rh, r1 = 2 * rh + 1;
        v0 = bias1; v1 = bias1;
        #pragma unroll
        for (int h = 0; h < 8; h++) {
            v0 += scratch[(h * 4 + r0) * 256 + c];
            v1 += scratch[(h * 4 + r1) * 256 + c];
        }
        const int wid  = tid >> 5;          // 0..15
        const int lane = tid & 31;
        float s0 = v0, q0 = v0 * v0, s1 = v1, q1 = v1 * v1;
        #pragma unroll
        for (int o = 16; o > 0; o >>= 1) {
            s0 += __shfl_xor_sync(0xffffffffu, s0, o);
            q0 += __shfl_xor_sync(0xffffffffu, q0, o);
            s1 += __shfl_xor_sync(0xffffffffu, s1, o);
            q1 += __shfl_xor_sync(0xffffffffu, q1, o);
        }
        if (lane == 0) {
            s_sum[wid][0] = s0; s_sq[wid][0] = q0;
            s_sum[wid][1] = s1; s_sq[wid][1] = q1;
        }
    }
    __syncthreads();

    // ---- per-thread LN finalize + GELU -> sh (rows 2rh, 2rh+1) ----
    {
        const int c  = tid & 255;
        const int w0 = 8 * rh;              // this row-pair's 8 partial warps
        float s0 = 0.f, q0 = 0.f, s1 = 0.f, q1 = 0.f;
        #pragma unroll
        for (int w = 0; w < 8; w++) {
            s0 += s_sum[w0 + w][0]; q0 += s_sq[w0 + w][0];
            s1 += s_sum[w0 + w][1]; q1 += s_sq[w0 + w][1];
        }
        const float m0 = s0 * (1.0f / HID);
        const float m1 = s1 * (1.0f / HID);
        const float rs0 = rsqrtf(q0 * (1.0f / HID) - m0 * m0 + 1e-5f);
        const float rs1 = rsqrtf(q1 * (1.0f / HID) - m1 * m1 + 1e-5f);
        sh[2 * rh + 0][c] = gelu_exact((v0 - m0) * rs0 * gg + bb);
        sh[2 * rh + 1][c] = gelu_exact((v1 - m1) * rs1 * gg + bb);
    }
    __syncthreads();

    // ---- GEMM2: cg2 = tid&31 -> cols 4cg2..+3, h2 = tid>>5 (16 slices) ->
    //      k in [16h2,16h2+16). W2 read once per block via LDG.128.
    //      scratch reuse is safe: its last readers were before the LN barrier. ----
    {
        const int cg2 = tid & 31;
        const int h2  = tid >> 5;           // 0..15
        const float* w2p = W2 + (size_t)(h2 * 16) * DIM + 4 * cg2;
        float4 a0 = make_float4(0.f, 0.f, 0.f, 0.f);
        float4 a1 = a0, a2 = a0, a3 = a0;
        #pragma unroll 4
        for (int kk = 0; kk < 16; kk++) {
            const float4 w4 = *reinterpret_cast<const float4*>(w2p + (size_t)kk * DIM);
            const int k = h2 * 16 + kk;
            const float g0 = sh[0][k];
            const float g1 = sh[1][k];
            const float g2 = sh[2][k];
            const float g3 = sh[3][k];
            a0.x = fmaf(g0, w4.x, a0.x); a0.y = fmaf(g0, w4.y, a0.y);
            a0.z = fmaf(g0, w4.z, a0.z); a0.w = fmaf(g0, w4.w, a0.w);
            a1.x = fmaf(g1, w4.x, a1.x); a1.y = fmaf(g1, w4.y, a1.y);
            a1.z = fmaf(g1, w4.z, a1.z); a1.w = fmaf(g1, w4.w, a1.w);
            a2.x = fmaf(g2, w4.x, a2.x); a2.y = fmaf(g2, w4.y, a2.y);
            a2.z = fmaf(g2, w4.z, a2.z); a2.w = fmaf(g2, w4.w, a2.w);
            a3.x = fmaf(g3, w4.x, a3.x); a3.y = fmaf(g3, w4.y, a3.y);
            a3.z = fmaf(g3, w4.z, a3.z); a3.w = fmaf(g3, w4.w, a3.w);
        }
        // p2[h2][r][c] = scratch[(h2*4+r)*128 + c]; STS.128 conflict-free
        float4* sc = reinterpret_cast<float4*>(scratch);
        sc[((h2 * 4 + 0) * 128 + 4 * cg2) >> 2] = a0;
        sc[((h2 * 4 + 1) * 128 + 4 * cg2) >> 2] = a1;
        sc[((h2 * 4 + 2) * 128 + 4 * cg2) >> 2] = a2;
        sc[((h2 * 4 + 3) * 128 + 4 * cg2) >> 2] = a3;
    }
    __syncthreads();

    // ---- combine GEMM2 k-partials + store (thread t -> r=t>>7, c=t&127) ----
    {
        const int r = tid >> 7;
        const int c = tid & (DIM - 1);
        float o = bias2;
        #pragma unroll
        for (int h2 = 0; h2 < 16; h2++)
            o += scratch[(h2 * 4 + r) * 128 + c];
        node_out[(size_t)(row0 + r) * DIM + c] = o;
    }
}

extern "C" void kernel_launch(void* const* d_in, const int* in_sizes, int n_in,
                              void* d_out, int out_size) {
    const float* x    = (const float*)d_in[0];
    const float* W1   = (const float*)d_in[1];
    const float* b1   = (const float*)d_in[2];
    const float* ln_g = (const float*)d_in[3];
    const float* ln_b = (const float*)d_in[4];
    const float* W2   = (const float*)d_in[5];
    const float* b2   = (const float*)d_in[6];
    const float* thr  = (const float*)d_in[11];

    float* out = (float*)d_out;
    float* adj_out  = out;                      // [1,1024,1024,1]
    float* node_out = out + NROWS * NROWS;      // [1,1024,128]

    fused_kernel<<<NBLOCKS, THREADS>>>(x, W1, b1, ln_g, ln_b, W2, b2, thr,
                                       adj_out, node_out);
}